// round 15
// baseline (speedup 1.0000x reference)
#include <cuda_runtime.h>
#include <cuda.h>
#include <cstdint>

#define D        64
#define E        6
#define WROWS    32                // rows per warp-tile
#define WHROWS   64                // half-rows per warp-tile (TMA box y)
#define THREADS  128
#define SLOT_BYTES 8192            // 32 rows * 256 B
#define OFF_SW     (8 * SLOT_BYTES)        // 65536 (W: 96 x 16B = 1536 B)
#define OFF_MB     (OFF_SW + 1536)         // 67072 (8 mbarriers, 8 B each)
#define SMEM_TOTAL (OFF_MB + 64 + 40)      // 67176

// ---------------- PTX helpers ----------------
__device__ __forceinline__ uint32_t smem_u32(const void* p) {
    uint32_t a;
    asm("{ .reg .u64 t; cvta.to.shared.u64 t, %1; cvt.u32.u64 %0, t; }" : "=r"(a) : "l"(p));
    return a;
}
#define MBAR_INIT(addr, cnt) \
    asm volatile("mbarrier.init.shared.b64 [%0], %1;" :: "r"(addr), "r"(cnt) : "memory")
#define MBAR_EXPECT_TX(addr, bytes) \
    asm volatile("mbarrier.arrive.expect_tx.shared.b64 _, [%0], %1;" :: "r"(addr), "r"(bytes) : "memory")
#define MBAR_WAIT(addr, parity) do {                                              \
    uint32_t _m = (addr), _p = (parity);                                          \
    asm volatile(                                                                 \
        "{\n\t.reg .pred P1;\n\t"                                                 \
        "WL_%=:\n\t"                                                              \
        "mbarrier.try_wait.parity.acquire.cta.shared::cta.b64 P1, [%0], %1, 0x989680;\n\t" \
        "@P1 bra.uni WD_%=;\n\t"                                                  \
        "bra.uni WL_%=;\n\t"                                                      \
        "WD_%=:\n\t}"                                                             \
        :: "r"(_m), "r"(_p) : "memory");                                          \
} while (0)
#define TMA_LOAD2D(dst, map, x, y, mbar) \
    asm volatile("cp.async.bulk.tensor.2d.shared::cta.global.tile.mbarrier::complete_tx::bytes " \
                 "[%0], [%1, {%2, %3}], [%4];" \
                 :: "r"(dst), "l"(map), "r"(x), "r"(y), "r"(mbar) : "memory")
#define FMA_F32X2(d, a, b, c) \
    asm("fma.rn.f32x2 %0, %1, %2, %3;" : "=l"(d) : "l"(a), "l"(b), "l"(c))
#define UNPACK2(lo, hi, v) \
    asm("mov.b64 {%0, %1}, %2;" : "=f"(lo), "=f"(hi) : "l"(v))

// ---------------- kernel ----------------
__global__ __launch_bounds__(THREADS)
void gate_kernel(const __grid_constant__ CUtensorMap tmap,
                 const float* __restrict__ W,
                 const float* __restrict__ b,
                 float* __restrict__ out,
                 int n, int ntiles)       // ntiles = ceil(n / WROWS)
{
    extern __shared__ char smem[];
    const uint32_t sbase = smem_u32(smem);
    const int tid  = threadIdx.x;
    const int wid  = tid >> 5;                   // warp id: owns its own pipeline
    const int lane = tid & 31;                   // == row index within warp-tile
    const int j0   = lane * 2;                   // first half-row index in warp-tile
    const int swz0 = j0 & 7;                     // SW128 phase of half 0 (even)
    const int swz1 = swz0 | 1;                   // phase of half 1

    // W staged in smem, flat layout: sw[e*16 + u] = W floats [e*64+u*4 .. +3].
    // All compute-loop W reads are warp-uniform -> pure LDS broadcast.
    ulonglong2* sw = reinterpret_cast<ulonglong2*>(smem + OFF_SW);
    if (tid < E * 16)
        sw[tid] = reinterpret_cast<const ulonglong2*>(W)[tid];
    if (tid < 8) MBAR_INIT(sbase + OFF_MB + 8 * tid, 1);

    // bias: 6 uniform cached loads, kept in registers
    float rb[E];
    #pragma unroll
    for (int e = 0; e < E; ++e) rb[e] = __ldg(b + e);

    __syncthreads();                             // W + mbarriers visible; last block sync

    // warp-private pipeline state
    const uint32_t mb0  = sbase + OFF_MB + wid * 16;      // slot 0 barrier
    const uint32_t mb1  = mb0 + 8;                        // slot 1 barrier
    const uint32_t slotB = sbase + wid * 2 * SLOT_BYTES;  // slot 0 data
    const int stride = gridDim.x * 4;
    const int t0 = blockIdx.x * 4 + wid;
    const CUtensorMap* mp = &tmap;

    auto prefetch = [&](int tile, int slot) {
        if (lane == 0) {
            uint32_t m = slot ? mb1 : mb0;
            MBAR_EXPECT_TX(m, SLOT_BYTES);
            TMA_LOAD2D(slotB + slot * SLOT_BYTES, mp, 0, tile * WHROWS, m);
        }
    };

    prefetch(t0, 0);
    if (t0 + stride < ntiles) prefetch(t0 + stride, 1);

    int ph0 = 0, ph1 = 0;
    for (int t = t0; t < ntiles; ) {
        #pragma unroll
        for (int s = 0; s < 2; ++s) {
            if (t >= ntiles) break;
            if (s == 0) { MBAR_WAIT(mb0, ph0); ph0 ^= 1; }
            else        { MBAR_WAIT(mb1, ph1); ph1 ^= 1; }

            long long row = (long long)t * WROWS + lane;
            const bool live = (row < n);

            uint64_t acc0[E], acc1[E];
            #pragma unroll
            for (int e = 0; e < E; ++e) { acc0[e] = 0ull; acc1[e] = 0ull; }

            if (live) {
                // half-rows of this row within the warp slot: j0 (phase swz0),
                // j0+1 (phase swz1); element unit u stored at u ^ phase
                const char* hb0 = reinterpret_cast<const char*>(smem)
                                + (wid * 2 + s) * SLOT_BYTES + j0 * 128;
                const char* hb1 = hb0 + 128;

                #pragma unroll
                for (int k = 0; k < 8; ++k) {
                    ulonglong2 hv0 = *reinterpret_cast<const ulonglong2*>(
                        hb0 + ((k ^ swz0) << 4));          // elements k*4 .. +3
                    ulonglong2 hv1 = *reinterpret_cast<const ulonglong2*>(
                        hb1 + ((k ^ swz1) << 4));          // elements 32+k*4 .. +3
                    #pragma unroll
                    for (int e = 0; e < E; ++e) {
                        ulonglong2 wv0 = sw[e * 16 + k];       // uniform -> broadcast
                        ulonglong2 wv1 = sw[e * 16 + 8 + k];
                        FMA_F32X2(acc0[e], hv0.x, wv0.x, acc0[e]);
                        FMA_F32X2(acc1[e], hv0.y, wv0.y, acc1[e]);
                        FMA_F32X2(acc0[e], hv1.x, wv1.x, acc0[e]);
                        FMA_F32X2(acc1[e], hv1.y, wv1.y, acc1[e]);
                    }
                }
            }

            // All LDS consumers (FMAs) precede this point in program order; per-lane
            // in-order issue => slot reads complete before lane 0 can reissue TMA.
            __syncwarp();
            int tn = t + 2 * stride;
            if (tn < ntiles) prefetch(tn, s);

            if (live) {
                float g[E];
                #pragma unroll
                for (int e = 0; e < E; ++e) {
                    float a0, a1, a2, a3;
                    UNPACK2(a0, a1, acc0[e]);
                    UNPACK2(a2, a3, acc1[e]);
                    g[e] = ((a0 + a2) + (a1 + a3)) + rb[e];
                }

                // top-2, strict >, earliest index wins (matches jax.lax.top_k)
                int i1 = 0; float m1 = g[0];
                #pragma unroll
                for (int e = 1; e < E; ++e) if (g[e] > m1) { m1 = g[e]; i1 = e; }
                int i2 = -1; float m2 = -3.402823466e+38f;
                #pragma unroll
                for (int e = 0; e < E; ++e) if (e != i1 && g[e] > m2) { m2 = g[e]; i2 = e; }

                float ex = __expf(m2 - m1);
                float p1 = 1.0f / (1.0f + ex);
                float p2 = ex * p1;

                float o[E];
                #pragma unroll
                for (int e = 0; e < E; ++e)
                    o[e] = (e == i1) ? p1 : ((e == i2) ? p2 : 0.0f);

                float2* op = reinterpret_cast<float2*>(out + row * (long long)E);
                op[0] = make_float2(o[0], o[1]);
                op[1] = make_float2(o[2], o[3]);
                op[2] = make_float2(o[4], o[5]);
            }

            t += stride;
        }
    }
}

// ---------------- host ----------------
typedef CUresult (*PFN_encodeTiled)(
    CUtensorMap*, CUtensorMapDataType, cuuint32_t, void*,
    const cuuint64_t*, const cuuint64_t*, const cuuint32_t*, const cuuint32_t*,
    CUtensorMapInterleave, CUtensorMapSwizzle, CUtensorMapL2promotion,
    CUtensorMapFloatOOBfill);

extern "C" void kernel_launch(void* const* d_in, const int* in_sizes, int n_in,
                              void* d_out, int out_size)
{
    const float* h = (const float*)d_in[0];
    const float* W = (const float*)d_in[1];
    const float* b = (const float*)d_in[2];
    float* out = (float*)d_out;

    int n = in_sizes[0] / D;
    int ntiles = (n + WROWS - 1) / WROWS;        // 32-row warp tiles

    // TMA descriptor: h viewed as 2D [32 floats x 2N half-rows], SW128.
    static PFN_encodeTiled encode = nullptr;
    if (!encode) {
        cudaDriverEntryPointQueryResult qr;
        void* fp = nullptr;
        cudaGetDriverEntryPointByVersion("cuTensorMapEncodeTiled", &fp, 12000,
                                         cudaEnableDefault, &qr);
        encode = (PFN_encodeTiled)fp;
    }

    CUtensorMap tmap;
    cuuint64_t dims[2]    = { 32, (cuuint64_t)n * 2 };
    cuuint64_t strides[1] = { 128 };
    cuuint32_t box[2]     = { 32, WHROWS };
    cuuint32_t estr[2]    = { 1, 1 };
    encode(&tmap, CU_TENSOR_MAP_DATA_TYPE_FLOAT32, 2, (void*)h,
           dims, strides, box, estr,
           CU_TENSOR_MAP_INTERLEAVE_NONE, CU_TENSOR_MAP_SWIZZLE_128B,
           CU_TENSOR_MAP_L2_PROMOTION_L2_128B, CU_TENSOR_MAP_FLOAT_OOB_FILL_NONE);

    cudaFuncSetAttribute(gate_kernel, cudaFuncAttributeMaxDynamicSharedMemorySize, SMEM_TOTAL);

    int grid = 148 * 3;                 // 3 blocks/SM resident (~65.6 KB smem each)
    int maxg = (ntiles + 3) / 4;
    if (grid > maxg) grid = maxg;
    gate_kernel<<<grid, THREADS, SMEM_TOTAL>>>(tmap, W, b, out, n, ntiles);
}

// round 16
// speedup vs baseline: 1.0303x; 1.0303x over previous
#include <cuda_runtime.h>
#include <cuda.h>
#include <cstdint>

#define D        64
#define E        6
#define ROWS     128               // rows per tile (one thread per row)
#define HROWS    256               // half-rows per tile (TMA box y)
#define THREADS  128
#define SLOT_BYTES 32768
#define OFF_SW     (2 * SLOT_BYTES)        // 65536 (W: 96 x 16B = 1536 B)
#define OFF_MB0    (OFF_SW + 1536)         // 67072
#define OFF_MB1    (OFF_MB0 + 8)           // 67080
#define SMEM_TOTAL (OFF_MB1 + 8 + 40)      // 67128

// ---------------- PTX helpers ----------------
__device__ __forceinline__ uint32_t smem_u32(const void* p) {
    uint32_t a;
    asm("{ .reg .u64 t; cvta.to.shared.u64 t, %1; cvt.u32.u64 %0, t; }" : "=r"(a) : "l"(p));
    return a;
}
#define MBAR_INIT(addr, cnt) \
    asm volatile("mbarrier.init.shared.b64 [%0], %1;" :: "r"(addr), "r"(cnt) : "memory")
#define MBAR_EXPECT_TX(addr, bytes) \
    asm volatile("mbarrier.arrive.expect_tx.shared.b64 _, [%0], %1;" :: "r"(addr), "r"(bytes) : "memory")
#define MBAR_WAIT(addr, parity) do {                                              \
    uint32_t _m = (addr), _p = (parity);                                          \
    asm volatile(                                                                 \
        "{\n\t.reg .pred P1;\n\t"                                                 \
        "WL_%=:\n\t"                                                              \
        "mbarrier.try_wait.parity.acquire.cta.shared::cta.b64 P1, [%0], %1, 0x989680;\n\t" \
        "@P1 bra.uni WD_%=;\n\t"                                                  \
        "bra.uni WL_%=;\n\t"                                                      \
        "WD_%=:\n\t}"                                                             \
        :: "r"(_m), "r"(_p) : "memory");                                          \
} while (0)
#define TMA_LOAD2D(dst, map, x, y, mbar) \
    asm volatile("cp.async.bulk.tensor.2d.shared::cta.global.tile.mbarrier::complete_tx::bytes " \
                 "[%0], [%1, {%2, %3}], [%4];" \
                 :: "r"(dst), "l"(map), "r"(x), "r"(y), "r"(mbar) : "memory")
#define FMA_F32X2(d, a, b, c) \
    asm("fma.rn.f32x2 %0, %1, %2, %3;" : "=l"(d) : "l"(a), "l"(b), "l"(c))
#define UNPACK2(lo, hi, v) \
    asm("mov.b64 {%0, %1}, %2;" : "=f"(lo), "=f"(hi) : "l"(v))

// ---------------- kernel ----------------
__global__ __launch_bounds__(THREADS)
void gate_kernel(const __grid_constant__ CUtensorMap tmap,
                 const float* __restrict__ W,
                 const float* __restrict__ b,
                 float* __restrict__ out,
                 int n, int ntiles)
{
    extern __shared__ char smem[];
    const uint32_t sbase = smem_u32(smem);
    const uint32_t mb[2] = { sbase + OFF_MB0, sbase + OFF_MB1 };
    const int tid  = threadIdx.x;                // == row index in tile
    const int j0   = tid * 2;                    // first half-row index
    const int swz0 = j0 & 7;                     // SW128 phase of half 0 (even)
    const int swz1 = swz0 | 1;                   // phase of half 1

    // W staged in smem, flat layout: sw[e*16 + u] = W floats [e*64+u*4 .. +3].
    // All compute-loop W reads are warp-uniform -> pure LDS broadcast.
    ulonglong2* sw = reinterpret_cast<ulonglong2*>(smem + OFF_SW);
    if (tid < E * 16)
        sw[tid] = reinterpret_cast<const ulonglong2*>(W)[tid];
    if (tid == 0) { MBAR_INIT(mb[0], 1); MBAR_INIT(mb[1], 1); }

    // bias: 6 uniform cached loads, kept in registers
    float rb[E];
    #pragma unroll
    for (int e = 0; e < E; ++e) rb[e] = __ldg(b + e);

    __syncthreads();

    const int stride = gridDim.x;
    const int t0 = blockIdx.x;
    const CUtensorMap* mp = &tmap;

    auto prefetch = [&](int tile, int slot) {
        if (tid == 0) {
            MBAR_EXPECT_TX(mb[slot], SLOT_BYTES);
            TMA_LOAD2D(sbase + slot * SLOT_BYTES, mp, 0, tile * HROWS, mb[slot]);
        }
    };

    prefetch(t0, 0);
    if (t0 + stride < ntiles) prefetch(t0 + stride, 1);

    int ph0 = 0, ph1 = 0;
    for (int t = t0; t < ntiles; ) {
        #pragma unroll
        for (int s = 0; s < 2; ++s) {
            if (t >= ntiles) break;
            if (s == 0) { MBAR_WAIT(mb[0], ph0); ph0 ^= 1; }
            else        { MBAR_WAIT(mb[1], ph1); ph1 ^= 1; }

            long long row = (long long)t * ROWS + tid;
            const bool live = (row < n);

            uint64_t acc0[E], acc1[E];
            #pragma unroll
            for (int e = 0; e < E; ++e) { acc0[e] = 0ull; acc1[e] = 0ull; }

            if (live) {
                // half-rows of this row: j0 at offset j0*128 (phase swz0),
                // j0+1 at +128 (phase swz1); element k at unit k ^ phase
                const char* hb0 = smem + s * SLOT_BYTES + j0 * 128;
                const char* hb1 = hb0 + 128;

                #pragma unroll
                for (int k = 0; k < 8; ++k) {
                    ulonglong2 hv0 = *reinterpret_cast<const ulonglong2*>(
                        hb0 + ((k ^ swz0) << 4));          // elements k*4 .. +3
                    ulonglong2 hv1 = *reinterpret_cast<const ulonglong2*>(
                        hb1 + ((k ^ swz1) << 4));          // elements 32+k*4 .. +3
                    #pragma unroll
                    for (int e = 0; e < E; ++e) {
                        ulonglong2 wv0 = sw[e * 16 + k];       // uniform -> broadcast
                        ulonglong2 wv1 = sw[e * 16 + 8 + k];
                        FMA_F32X2(acc0[e], hv0.x, wv0.x, acc0[e]);
                        FMA_F32X2(acc1[e], hv0.y, wv0.y, acc1[e]);
                        FMA_F32X2(acc0[e], hv1.x, wv1.x, acc0[e]);
                        FMA_F32X2(acc1[e], hv1.y, wv1.y, acc1[e]);
                    }
                }
            }

            // smem reads for slot s are done -> release the slot and refill it
            // BEFORE the epilogue, so the TMA overlaps the tail computation.
            __syncthreads();
            int tn = t + 2 * stride;
            if (tn < ntiles) prefetch(tn, s);

            if (live) {
                float g[E];
                #pragma unroll
                for (int e = 0; e < E; ++e) {
                    float a0, a1, a2, a3;
                    UNPACK2(a0, a1, acc0[e]);
                    UNPACK2(a2, a3, acc1[e]);
                    g[e] = ((a0 + a2) + (a1 + a3)) + rb[e];
                }

                // top-2, strict >, earliest index wins (matches jax.lax.top_k)
                int i1 = 0; float m1 = g[0];
                #pragma unroll
                for (int e = 1; e < E; ++e) if (g[e] > m1) { m1 = g[e]; i1 = e; }
                int i2 = -1; float m2 = -3.402823466e+38f;
                #pragma unroll
                for (int e = 0; e < E; ++e) if (e != i1 && g[e] > m2) { m2 = g[e]; i2 = e; }

                float ex = __expf(m2 - m1);
                float p1 = 1.0f / (1.0f + ex);
                float p2 = ex * p1;

                float o[E];
                #pragma unroll
                for (int e = 0; e < E; ++e)
                    o[e] = (e == i1) ? p1 : ((e == i2) ? p2 : 0.0f);

                float2* op = reinterpret_cast<float2*>(out + row * (long long)E);
                op[0] = make_float2(o[0], o[1]);
                op[1] = make_float2(o[2], o[3]);
                op[2] = make_float2(o[4], o[5]);
            }

            t += stride;
        }
    }
}

// ---------------- host ----------------
typedef CUresult (*PFN_encodeTiled)(
    CUtensorMap*, CUtensorMapDataType, cuuint32_t, void*,
    const cuuint64_t*, const cuuint64_t*, const cuuint32_t*, const cuuint32_t*,
    CUtensorMapInterleave, CUtensorMapSwizzle, CUtensorMapL2promotion,
    CUtensorMapFloatOOBfill);

extern "C" void kernel_launch(void* const* d_in, const int* in_sizes, int n_in,
                              void* d_out, int out_size)
{
    const float* h = (const float*)d_in[0];
    const float* W = (const float*)d_in[1];
    const float* b = (const float*)d_in[2];
    float* out = (float*)d_out;

    int n = in_sizes[0] / D;
    int ntiles = (n + ROWS - 1) / ROWS;

    // TMA descriptor: h viewed as 2D [32 floats x 2N half-rows], SW128.
    // L2_256B promotion: fills are perfectly sequential 32KB tiles, so wider
    // promotion halves L2 request/tag overhead on the fill path.
    static PFN_encodeTiled encode = nullptr;
    if (!encode) {
        cudaDriverEntryPointQueryResult qr;
        void* fp = nullptr;
        cudaGetDriverEntryPointByVersion("cuTensorMapEncodeTiled", &fp, 12000,
                                         cudaEnableDefault, &qr);
        encode = (PFN_encodeTiled)fp;
    }

    CUtensorMap tmap;
    cuuint64_t dims[2]    = { 32, (cuuint64_t)n * 2 };
    cuuint64_t strides[1] = { 128 };
    cuuint32_t box[2]     = { 32, HROWS };
    cuuint32_t estr[2]    = { 1, 1 };
    encode(&tmap, CU_TENSOR_MAP_DATA_TYPE_FLOAT32, 2, (void*)h,
           dims, strides, box, estr,
           CU_TENSOR_MAP_INTERLEAVE_NONE, CU_TENSOR_MAP_SWIZZLE_128B,
           CU_TENSOR_MAP_L2_PROMOTION_L2_256B, CU_TENSOR_MAP_FLOAT_OOB_FILL_NONE);

    cudaFuncSetAttribute(gate_kernel, cudaFuncAttributeMaxDynamicSharedMemorySize, SMEM_TOTAL);

    int grid = 148 * 3;                 // 3 blocks/SM resident (~65.6 KB smem each)
    if (grid > ntiles) grid = ntiles;
    gate_kernel<<<grid, THREADS, SMEM_TOTAL>>>(tmap, W, b, out, n, ntiles);
}

// round 17
// speedup vs baseline: 1.0702x; 1.0387x over previous
#include <cuda_runtime.h>
#include <cuda.h>
#include <cstdint>

#define D        64
#define E        6
#define ROWS     128               // rows per tile (one thread per row)
#define HROWS    256               // half-rows per tile (TMA box y)
#define THREADS  128
#define SLOT_BYTES 32768
#define OFF_SW     (2 * SLOT_BYTES)        // 65536 (W: 96 x 16B = 1536 B)
#define OFF_MB0    (OFF_SW + 1536)         // 67072
#define OFF_MB1    (OFF_MB0 + 8)           // 67080
#define SMEM_TOTAL (OFF_MB1 + 8 + 40)      // 67128

// ---------------- PTX helpers ----------------
__device__ __forceinline__ uint32_t smem_u32(const void* p) {
    uint32_t a;
    asm("{ .reg .u64 t; cvta.to.shared.u64 t, %1; cvt.u32.u64 %0, t; }" : "=r"(a) : "l"(p));
    return a;
}
#define MBAR_INIT(addr, cnt) \
    asm volatile("mbarrier.init.shared.b64 [%0], %1;" :: "r"(addr), "r"(cnt) : "memory")
#define MBAR_EXPECT_TX(addr, bytes) \
    asm volatile("mbarrier.arrive.expect_tx.shared.b64 _, [%0], %1;" :: "r"(addr), "r"(bytes) : "memory")
#define MBAR_WAIT(addr, parity) do {                                              \
    uint32_t _m = (addr), _p = (parity);                                          \
    asm volatile(                                                                 \
        "{\n\t.reg .pred P1;\n\t"                                                 \
        "WL_%=:\n\t"                                                              \
        "mbarrier.try_wait.parity.acquire.cta.shared::cta.b64 P1, [%0], %1, 0x989680;\n\t" \
        "@P1 bra.uni WD_%=;\n\t"                                                  \
        "bra.uni WL_%=;\n\t"                                                      \
        "WD_%=:\n\t}"                                                             \
        :: "r"(_m), "r"(_p) : "memory");                                          \
} while (0)
#define TMA_LOAD2D(dst, map, x, y, mbar) \
    asm volatile("cp.async.bulk.tensor.2d.shared::cta.global.tile.mbarrier::complete_tx::bytes " \
                 "[%0], [%1, {%2, %3}], [%4];" \
                 :: "r"(dst), "l"(map), "r"(x), "r"(y), "r"(mbar) : "memory")
#define FMA_F32X2(d, a, b, c) \
    asm("fma.rn.f32x2 %0, %1, %2, %3;" : "=l"(d) : "l"(a), "l"(b), "l"(c))
#define UNPACK2(lo, hi, v) \
    asm("mov.b64 {%0, %1}, %2;" : "=f"(lo), "=f"(hi) : "l"(v))

// ---------------- kernel ----------------
__global__ __launch_bounds__(THREADS)
void gate_kernel(const __grid_constant__ CUtensorMap tmap,
                 const float* __restrict__ W,
                 const float* __restrict__ b,
                 float* __restrict__ out,
                 int n, int ntiles)
{
    extern __shared__ char smem[];
    const uint32_t sbase = smem_u32(smem);
    const uint32_t mb[2] = { sbase + OFF_MB0, sbase + OFF_MB1 };
    const int tid  = threadIdx.x;                // == row index in tile
    const int j0   = tid * 2;                    // first half-row index
    const int swz0 = j0 & 7;                     // SW128 phase of half 0 (even)
    const int swz1 = swz0 | 1;                   // phase of half 1

    // W staged in smem, flat layout: sw[e*16 + u] = W floats [e*64+u*4 .. +3].
    // All compute-loop W reads are warp-uniform -> pure LDS broadcast.
    ulonglong2* sw = reinterpret_cast<ulonglong2*>(smem + OFF_SW);
    if (tid < E * 16)
        sw[tid] = reinterpret_cast<const ulonglong2*>(W)[tid];
    if (tid == 0) { MBAR_INIT(mb[0], 1); MBAR_INIT(mb[1], 1); }

    // bias: 6 uniform cached loads, kept in registers
    float rb[E];
    #pragma unroll
    for (int e = 0; e < E; ++e) rb[e] = __ldg(b + e);

    __syncthreads();

    const int stride = gridDim.x;
    const int t0 = blockIdx.x;
    const CUtensorMap* mp = &tmap;

    auto prefetch = [&](int tile, int slot) {
        if (tid == 0) {
            MBAR_EXPECT_TX(mb[slot], SLOT_BYTES);
            TMA_LOAD2D(sbase + slot * SLOT_BYTES, mp, 0, tile * HROWS, mb[slot]);
        }
    };

    prefetch(t0, 0);
    if (t0 + stride < ntiles) prefetch(t0 + stride, 1);

    int ph0 = 0, ph1 = 0;
    for (int t = t0; t < ntiles; ) {
        #pragma unroll
        for (int s = 0; s < 2; ++s) {
            if (t >= ntiles) break;
            if (s == 0) { MBAR_WAIT(mb[0], ph0); ph0 ^= 1; }
            else        { MBAR_WAIT(mb[1], ph1); ph1 ^= 1; }

            long long row = (long long)t * ROWS + tid;
            const bool live = (row < n);

            uint64_t acc0[E], acc1[E];
            #pragma unroll
            for (int e = 0; e < E; ++e) { acc0[e] = 0ull; acc1[e] = 0ull; }

            if (live) {
                // half-rows of this row: j0 at offset j0*128 (phase swz0),
                // j0+1 at +128 (phase swz1); element k at unit k ^ phase
                const char* hb0 = smem + s * SLOT_BYTES + j0 * 128;
                const char* hb1 = hb0 + 128;

                #pragma unroll
                for (int k = 0; k < 8; ++k) {
                    ulonglong2 hv0 = *reinterpret_cast<const ulonglong2*>(
                        hb0 + ((k ^ swz0) << 4));          // elements k*4 .. +3
                    ulonglong2 hv1 = *reinterpret_cast<const ulonglong2*>(
                        hb1 + ((k ^ swz1) << 4));          // elements 32+k*4 .. +3
                    #pragma unroll
                    for (int e = 0; e < E; ++e) {
                        ulonglong2 wv0 = sw[e * 16 + k];       // uniform -> broadcast
                        ulonglong2 wv1 = sw[e * 16 + 8 + k];
                        FMA_F32X2(acc0[e], hv0.x, wv0.x, acc0[e]);
                        FMA_F32X2(acc1[e], hv0.y, wv0.y, acc1[e]);
                        FMA_F32X2(acc0[e], hv1.x, wv1.x, acc0[e]);
                        FMA_F32X2(acc1[e], hv1.y, wv1.y, acc1[e]);
                    }
                }
            }

            // smem reads for slot s are done -> release the slot and refill it
            // BEFORE the epilogue, so the TMA overlaps the tail computation.
            __syncthreads();
            int tn = t + 2 * stride;
            if (tn < ntiles) prefetch(tn, s);

            if (live) {
                float g[E];
                #pragma unroll
                for (int e = 0; e < E; ++e) {
                    float a0, a1, a2, a3;
                    UNPACK2(a0, a1, acc0[e]);
                    UNPACK2(a2, a3, acc1[e]);
                    g[e] = ((a0 + a2) + (a1 + a3)) + rb[e];
                }

                // top-2, strict >, earliest index wins (matches jax.lax.top_k)
                int i1 = 0; float m1 = g[0];
                #pragma unroll
                for (int e = 1; e < E; ++e) if (g[e] > m1) { m1 = g[e]; i1 = e; }
                int i2 = -1; float m2 = -3.402823466e+38f;
                #pragma unroll
                for (int e = 0; e < E; ++e) if (e != i1 && g[e] > m2) { m2 = g[e]; i2 = e; }

                float ex = __expf(m2 - m1);
                float p1 = 1.0f / (1.0f + ex);
                float p2 = ex * p1;

                float o[E];
                #pragma unroll
                for (int e = 0; e < E; ++e)
                    o[e] = (e == i1) ? p1 : ((e == i2) ? p2 : 0.0f);

                float2* op = reinterpret_cast<float2*>(out + row * (long long)E);
                op[0] = make_float2(o[0], o[1]);
                op[1] = make_float2(o[2], o[3]);
                op[2] = make_float2(o[4], o[5]);
            }

            t += stride;
        }
    }
}

// ---------------- host ----------------
typedef CUresult (*PFN_encodeTiled)(
    CUtensorMap*, CUtensorMapDataType, cuuint32_t, void*,
    const cuuint64_t*, const cuuint64_t*, const cuuint32_t*, const cuuint32_t*,
    CUtensorMapInterleave, CUtensorMapSwizzle, CUtensorMapL2promotion,
    CUtensorMapFloatOOBfill);

extern "C" void kernel_launch(void* const* d_in, const int* in_sizes, int n_in,
                              void* d_out, int out_size)
{
    const float* h = (const float*)d_in[0];
    const float* W = (const float*)d_in[1];
    const float* b = (const float*)d_in[2];
    float* out = (float*)d_out;

    int n = in_sizes[0] / D;
    int ntiles = (n + ROWS - 1) / ROWS;

    // TMA descriptor: h viewed as 2D [32 floats x 2N half-rows], SW128, L2_128B.
    static PFN_encodeTiled encode = nullptr;
    if (!encode) {
        cudaDriverEntryPointQueryResult qr;
        void* fp = nullptr;
        cudaGetDriverEntryPointByVersion("cuTensorMapEncodeTiled", &fp, 12000,
                                         cudaEnableDefault, &qr);
        encode = (PFN_encodeTiled)fp;
    }

    CUtensorMap tmap;
    cuuint64_t dims[2]    = { 32, (cuuint64_t)n * 2 };
    cuuint64_t strides[1] = { 128 };
    cuuint32_t box[2]     = { 32, HROWS };
    cuuint32_t estr[2]    = { 1, 1 };
    encode(&tmap, CU_TENSOR_MAP_DATA_TYPE_FLOAT32, 2, (void*)h,
           dims, strides, box, estr,
           CU_TENSOR_MAP_INTERLEAVE_NONE, CU_TENSOR_MAP_SWIZZLE_128B,
           CU_TENSOR_MAP_L2_PROMOTION_L2_128B, CU_TENSOR_MAP_FLOAT_OOB_FILL_NONE);

    cudaFuncSetAttribute(gate_kernel, cudaFuncAttributeMaxDynamicSharedMemorySize, SMEM_TOTAL);

    int grid = 148 * 3;                 // 3 blocks/SM resident (~65.6 KB smem each)
    if (grid > ntiles) grid = ntiles;
    gate_kernel<<<grid, THREADS, SMEM_TOTAL>>>(tmap, W, b, out, n, ntiles);
}